// round 11
// baseline (speedup 1.0000x reference)
#include <cuda_runtime.h>
#include <cuda_bf16.h>
#include <cstdint>

// Word2DM loss via factored Gram identity:
//   sims(b, X) = sum_{a<=b} w_ab * Gt[a,b] * Gx[a,b],  G = B B^T (over m)
// Gx depends ONLY on the vocab row -> precompute Gtab[v] as bf16 (weights
// baked in, 48 MB, L2-resident). Gram pass: persistent blocks (8 groups,
// double-buffered cp.async) + smem-staged COALESCED table writes.
// Main pass: raw Gt once per sample, 11 unrolled gather-dot phases.

#define NDIM 20
#define ROWF 400
#define ROW4 100
#define SPB  8
#define TPS  20
#define TPB  (SPB * TPS)        // 160
#define GSTRIDE 84              // words per 4-row group (4*20 + 4 pad)
#define SSTRIDE 424             // words per sample tile (5*84 + 4 pad)
#define VCAP  100000
#define GROWU 120               // u32 per vocab row in Gtab (10 roles x 12)
#define KMAX  16
#define KNEG  10                // fast path (this problem instance)
#define GPB   8                 // vocab groups per gram block

__device__ uint32_t Gtab32[(size_t)VCAP * GROWU];   // 48 MB scratch (bf16x2)

__device__ __forceinline__ float red2(uint64_t v) {
    float lo, hi; asm("mov.b64 {%0,%1},%2;" : "=f"(lo), "=f"(hi) : "l"(v));
    return lo + hi;
}
__device__ __forceinline__ uint64_t pack2f(float a, float b) {
    uint64_t r; asm("mov.b64 %0,{%1,%2};" : "=l"(r) : "f"(a), "f"(b));
    return r;
}
__device__ __forceinline__ uint64_t ffma2(uint64_t a, uint64_t b, uint64_t c) {
    uint64_t r; asm("fma.rn.f32x2 %0,%1,%2,%3;" : "=l"(r) : "l"(a), "l"(b), "l"(c));
    return r;
}
__device__ __forceinline__ uint64_t dot5p(const uint64_t* x, const uint64_t* y) {
    uint64_t acc = 0;
    #pragma unroll
    for (int q = 0; q < 5; q++) acc = ffma2(x[q], y[q], acc);
    return acc;
}
__device__ __forceinline__ uint32_t bfpack(float a, float b) {
    __nv_bfloat162 t = __floats2bfloat162_rn(a, b);
    return *reinterpret_cast<uint32_t*>(&t);
}
__device__ __forceinline__ uint64_t bf2f2(uint32_t v) {
    float2 f = __bfloat1622float2(*reinterpret_cast<__nv_bfloat162*>(&v));
    return pack2f(f.x, f.y);
}

__device__ __forceinline__ void cp16(float* smp, const float* g) {
    unsigned a = (unsigned)__cvta_generic_to_shared(smp);
    asm volatile("cp.async.cg.shared.global [%0], [%1], 16;" :: "r"(a), "l"(g));
}
#define CP_COMMIT()  asm volatile("cp.async.commit_group;")
#define CP_WAIT1()   asm volatile("cp.async.wait_group 1;")
#define CP_WAIT0()   asm volatile("cp.async.wait_group 0;")

// Raw 21 pair-dots for one sample tile; both m-halves end holding full dots.
__device__ __forceinline__ void gram21(const float* tile, int ob, int fb0,
                                       int role, float* g)
{
    const uint64_t* tb = (const uint64_t*)tile;
    uint64_t o[4][5];
    #pragma unroll
    for (int a = 0; a < 4; a++)
        #pragma unroll
        for (int q = 0; q < 5; q++) o[a][q] = tb[ob + a * 10 + q];

    #pragma unroll
    for (int fb = 0; fb < 4; fb++) {
        uint64_t f[5];
        #pragma unroll
        for (int q = 0; q < 5; q++) f[q] = tb[fb0 + fb * 10 + q];
        #pragma unroll
        for (int a = 0; a < 4; a++) g[fb * 4 + a] = red2(dot5p(o[a], f));
    }
    if (role < 5) {
        g[16] = red2(dot5p(o[0], o[0])); g[17] = red2(dot5p(o[0], o[1]));
        g[18] = red2(dot5p(o[0], o[2])); g[19] = red2(dot5p(o[0], o[3]));
        g[20] = red2(dot5p(o[1], o[1]));
    } else {
        g[16] = red2(dot5p(o[1], o[2])); g[17] = red2(dot5p(o[1], o[3]));
        g[18] = red2(dot5p(o[2], o[2])); g[19] = red2(dot5p(o[2], o[3]));
        g[20] = red2(dot5p(o[3], o[3]));
    }
    #pragma unroll
    for (int i = 0; i < 21; i++)
        g[i] += __shfl_xor_sync(0xffffffffu, g[i], 1);
}

// ------- Kernel 1: weighted bf16 Gram table (persistent, coalesced) -------
__global__ __launch_bounds__(TPB) void w2dm_gram(
    const float* __restrict__ Wc, int vocab, float* __restrict__ out)
{
    if (blockIdx.x == 0 && threadIdx.x == 0) out[0] = 0.0f;

    __shared__ float    buf[2][SPB * SSTRIDE];
    __shared__ uint32_t gbuf[SPB * GROWU];

    const int tid  = threadIdx.x;
    const int s    = tid / TPS;
    const int p    = tid % TPS;
    const int role = p >> 1;
    const int h    = p & 1;
    const int gown = role % 5;
    const int gfor = (role + 1 + (role >= 5 ? 1 : 0)) % 5;
    const int ob  = gown * 42 + 5 * h;
    const int fb0 = gfor * 42 + 5 * h;

    const int ngroups = (vocab + SPB - 1) / SPB;
    const int g0 = blockIdx.x * GPB;
    const int gn = (g0 + GPB < ngroups) ? GPB : (ngroups - g0);
    if (gn <= 0) return;

    auto stage = [&](int gi, int slot) {
        const int v0 = (g0 + gi) * SPB;
        #pragma unroll
        for (int k = 0; k < 5; k++) {
            const int i  = tid + k * TPB;
            const int ss = i / ROW4;
            const int e4 = i % ROW4;
            const int n  = e4 / 5;
            const int j  = e4 % 5;
            int v = v0 + ss; if (v >= vocab) v = vocab - 1;
            cp16(buf[slot] + ss * SSTRIDE + (n >> 2) * GSTRIDE + (n & 3) * 20 + j * 4,
                 Wc + (size_t)v * ROWF + e4 * 4);
        }
        CP_COMMIT();
    };

    stage(0, 0);
    for (int gi = 0; gi < gn; gi++) {
        if (gi + 1 < gn) { stage(gi + 1, (gi + 1) & 1); CP_WAIT1(); }
        else             { CP_WAIT0(); }
        __syncthreads();               // tile gi ready; gbuf free (prev stores done)

        float g[21];
        gram21(buf[gi & 1] + s * SSTRIDE, ob, fb0, role, g);

        // bake weights
        #pragma unroll
        for (int i = 0; i < 16; i++) g[i] *= 2.0f;
        {
            const bool A = (role < 5);
            const float wv[5] = { A ? 1.f : 2.f, 2.f, A ? 2.f : 1.f, 2.f, 1.f };
            #pragma unroll
            for (int i = 0; i < 5; i++) g[16 + i] *= wv[i];
        }

        // stage into smem in exact table-row layout
        uint32_t* dst = gbuf + s * GROWU + role * 12 + h * 6;
        if (h == 0) {
            dst[0] = bfpack(g[0],  g[1]);  dst[1] = bfpack(g[2],  g[3]);
            dst[2] = bfpack(g[4],  g[5]);  dst[3] = bfpack(g[6],  g[7]);
            dst[4] = bfpack(g[8],  g[9]);  dst[5] = bfpack(g[10], g[11]);
        } else {
            dst[0] = bfpack(g[12], g[13]); dst[1] = bfpack(g[14], g[15]);
            dst[2] = bfpack(g[16], g[17]); dst[3] = bfpack(g[18], g[19]);
            dst[4] = bfpack(g[20], 0.f);   dst[5] = 0u;
        }
        __syncthreads();               // gbuf complete

        // coalesced table write (960 consecutive u32)
        const int v0 = (g0 + gi) * SPB;
        const size_t base = (size_t)v0 * GROWU;
        #pragma unroll
        for (int k = 0; k < (SPB * GROWU) / TPB; k++) {
            const int i = tid + k * TPB;
            if (v0 + i / GROWU < vocab) Gtab32[base + i] = gbuf[i];
        }
    }
}

// ---------------- Kernel 2: main pass ----------------
__global__ __launch_bounds__(TPB) void w2dm_main(
    const float* __restrict__ Wt,
    const int*   __restrict__ tgt,
    const int*   __restrict__ ctx,
    const int*   __restrict__ neg,
    float*       __restrict__ out,
    int batch, int kneg, float inv_batch)
{
    __shared__ float buf[SPB * SSTRIDE];
    __shared__ float part[(KMAX + 1) * TPB];
    __shared__ float termbuf[SPB * (KMAX + 1)];
    __shared__ int   sidx[SPB * (KMAX + 2)];

    const int tid  = threadIdx.x;
    const int s    = tid / TPS;
    const int p    = tid % TPS;
    const int role = p >> 1;
    const int h    = p & 1;
    const int gown = role % 5;
    const int gfor = (role + 1 + (role >= 5 ? 1 : 0)) % 5;
    const int ob  = gown * 42 + 5 * h;
    const int fb0 = gfor * 42 + 5 * h;
    const int sample0 = blockIdx.x * SPB;

    for (int i = tid; i < SPB * (2 + kneg); i += TPB) {
        int v;
        if (i < SPB) {
            const int smp = sample0 + i;
            v = (smp < batch) ? tgt[smp] : 0;
        } else if (i < 2 * SPB) {
            const int smp = sample0 + (i - SPB);
            v = (smp < batch) ? ctx[smp] : 0;
        } else {
            const int q = i - 2 * SPB;
            const int smp = sample0 + q / kneg;
            v = (smp < batch) ? neg[(size_t)smp * kneg + (q % kneg)] : 0;
        }
        sidx[i] = v;
    }
    __syncthreads();

    #pragma unroll
    for (int k = 0; k < 5; k++) {
        const int i  = tid + k * TPB;
        const int ss = i / ROW4;
        const int e4 = i % ROW4;
        const int n  = e4 / 5;
        const int j  = e4 % 5;
        cp16(buf + ss * SSTRIDE + (n >> 2) * GSTRIDE + (n & 3) * 20 + j * 4,
             Wt + (size_t)sidx[ss] * ROWF + e4 * 4);
    }
    CP_COMMIT();
    CP_WAIT0();
    __syncthreads();

    float g[21];
    gram21(buf + s * SSTRIDE, ob, fb0, role, g);
    uint64_t gtp[6];
    if (h == 0) {
        #pragma unroll
        for (int i = 0; i < 6; i++) gtp[i] = pack2f(g[2*i], g[2*i+1]);
    } else {
        gtp[0] = pack2f(g[12], g[13]); gtp[1] = pack2f(g[14], g[15]);
        gtp[2] = pack2f(g[16], g[17]); gtp[3] = pack2f(g[18], g[19]);
        gtp[4] = pack2f(g[20], 0.f);   gtp[5] = 0;
    }

    const size_t gtoff = (size_t)(role * 12 + h * 6);   // u32 units
    auto phase = [&](int k) {
        const int idx = (k == 0) ? sidx[SPB + s]
                                 : sidx[2 * SPB + s * kneg + (k - 1)];
        const uint2* gp = (const uint2*)(Gtab32 + (size_t)idx * GROWU + gtoff);
        uint2 w0 = gp[0], w1 = gp[1], w2 = gp[2];
        uint64_t acc = 0;
        acc = ffma2(bf2f2(w0.x), gtp[0], acc);
        acc = ffma2(bf2f2(w0.y), gtp[1], acc);
        acc = ffma2(bf2f2(w1.x), gtp[2], acc);
        acc = ffma2(bf2f2(w1.y), gtp[3], acc);
        acc = ffma2(bf2f2(w2.x), gtp[4], acc);
        acc = ffma2(bf2f2(w2.y), gtp[5], acc);
        part[k * TPB + s * TPS + p] = red2(acc);
    };
    if (kneg == KNEG) {
        #pragma unroll
        for (int k = 0; k <= KNEG; k++) phase(k);
    } else {
        for (int k = 0; k <= kneg; k++) phase(k);
    }

    __syncthreads();
    const int nterm = kneg + 1;
    const int ntask = SPB * nterm;
    for (int t = tid; t < ntask; t += TPB) {
        const int ss = t / nterm;
        const int kk = t % nterm;
        float sims = 0.0f;
        const float* pr = part + kk * TPB + ss * TPS;
        #pragma unroll
        for (int i = 0; i < TPS; i++) sims += pr[i];
        termbuf[t] = ((sample0 + ss) < batch)
                   ? log1pf(expf(kk == 0 ? -sims : sims)) : 0.0f;
    }
    __syncthreads();
    if (tid < 32) {
        float v = 0.0f;
        for (int t = tid; t < ntask; t += 32) v += termbuf[t];
        #pragma unroll
        for (int off = 16; off > 0; off >>= 1)
            v += __shfl_xor_sync(0xffffffffu, v, off);
        if (tid == 0) atomicAdd(out, v * inv_batch);
    }
}

extern "C" void kernel_launch(void* const* d_in, const int* in_sizes, int n_in,
                              void* d_out, int out_size)
{
    const float* Wt  = (const float*)d_in[0];
    const float* Wc  = (const float*)d_in[1];
    const int*   tgt = (const int*)d_in[2];
    const int*   ctx = (const int*)d_in[3];
    const int*   neg = (const int*)d_in[4];
    float*       out = (float*)d_out;

    const int batch = in_sizes[2];
    int kneg  = in_sizes[4] / batch;
    if (kneg > KMAX) kneg = KMAX;
    int vocab = in_sizes[1] / ROWF;
    if (vocab > VCAP) vocab = VCAP;
    const float inv_batch = 1.0f / (float)batch;

    const int ngroups = (vocab + SPB - 1) / SPB;
    const int ggrid = (ngroups + GPB - 1) / GPB;
    w2dm_gram<<<ggrid, TPB>>>(Wc, vocab, out);

    const int mgrid = (batch + SPB - 1) / SPB;
    w2dm_main<<<mgrid, TPB>>>(Wt, tgt, ctx, neg, out, batch, kneg, inv_batch);
}